// round 6
// baseline (speedup 1.0000x reference)
#include <cuda_runtime.h>
#include <cstdint>
#include <cstddef>

#define NN   384
#define DIN  128
#define HID  256
#define HID2 128

// ---------------- scratch (device globals: allocation-free) ----------------
__device__ float g_H0[NN * HID];                 // tf32-rounded z@W1[:128]
__device__ float g_A [(size_t)NN * NN * HID];    // relu(P@H0 + corr) : 151 MB
__device__ float g_t3[NN * HID];
__device__ float g_v [NN * NN];
__device__ float g_S [NN * NN];

// ---------------- helpers ----------------
__device__ __forceinline__ uint32_t f2tf(float x) {
    uint32_t r;
    asm("cvt.rna.tf32.f32 %0, %1;" : "=r"(r) : "f"(x));
    return r;
}
__device__ __forceinline__ uint32_t asu(float x) { return __float_as_uint(x); }

__device__ __forceinline__ void mma_tf32(float* c, const uint32_t* a, const uint32_t* b) {
    asm volatile(
        "mma.sync.aligned.m16n8k8.row.col.f32.tf32.tf32.f32 "
        "{%0,%1,%2,%3}, {%4,%5,%6,%7}, {%8,%9}, {%0,%1,%2,%3};\n"
        : "+f"(c[0]), "+f"(c[1]), "+f"(c[2]), "+f"(c[3])
        : "r"(a[0]), "r"(a[1]), "r"(a[2]), "r"(a[3]), "r"(b[0]), "r"(b[1]));
}

__device__ __forceinline__ void cpa16(uint32_t saddr, const void* gaddr) {
    asm volatile("cp.async.cg.shared.global [%0], [%1], 16;" :: "r"(saddr), "l"(gaddr));
}
__device__ __forceinline__ void cpa_commit() {
    asm volatile("cp.async.commit_group;");
}
template <int N>
__device__ __forceinline__ void cpa_wait() {
    asm volatile("cp.async.wait_group %0;" :: "n"(N));
}

#define AS_STRIDE 36
#define BS_STRIDE 136
#define AS_BUF (128 * AS_STRIDE)   // 4608 floats
#define BS_BUF (32  * BS_STRIDE)   // 4352 floats

// 128x32 tile global->smem via cp.async (128 threads)
__device__ __forceinline__ void cp_tileA(float* As, const float* __restrict__ src,
                                         int ldm, int tid) {
#pragma unroll
    for (int i = 0; i < 8; i++) {
        int f = tid + 128 * i;
        int row = f >> 3, c4 = f & 7;
        cpa16((uint32_t)__cvta_generic_to_shared(As + row * AS_STRIDE + c4 * 4),
              src + (size_t)row * ldm + c4 * 4);
    }
}
// 32x128 tile global->smem via cp.async (128 threads)
__device__ __forceinline__ void cp_tileB(float* Bs, const float* __restrict__ src,
                                         int ldm, int tid) {
#pragma unroll
    for (int i = 0; i < 8; i++) {
        int f = tid + 128 * i;
        int row = f >> 5, c4 = f & 31;
        cpa16((uint32_t)__cvta_generic_to_shared(Bs + row * BS_STRIDE + c4 * 4),
              src + (size_t)row * ldm + c4 * 4);
    }
}

// one 32-deep k-tile of 128x128 CTA GEMM; 4 warps (2x2), warp tile 64x64.
// A fragments cvt.rna->tf32 (raw P bits); B (H0) pre-rounded tf32.
__device__ __forceinline__ void compute_ktile64(float (&c)[4][8][4],
                                                const float* __restrict__ As,
                                                const float* __restrict__ Bs,
                                                int rA, int cB, int g, int t4) {
#pragma unroll
    for (int kk = 0; kk < 4; kk++) {
        const int k = kk * 8;
        uint32_t a[4][4];
#pragma unroll
        for (int tm = 0; tm < 4; tm++) {
            const float* ap = As + (rA + tm * 16 + g) * AS_STRIDE + k + t4;
            a[tm][0] = f2tf(ap[0]);
            a[tm][1] = f2tf(ap[8 * AS_STRIDE]);
            a[tm][2] = f2tf(ap[4]);
            a[tm][3] = f2tf(ap[8 * AS_STRIDE + 4]);
        }
        uint32_t bb[8][2];
#pragma unroll
        for (int tn = 0; tn < 8; tn++) {
            const float* bp = Bs + (k + t4) * BS_STRIDE + cB + tn * 8 + g;
            bb[tn][0] = asu(bp[0]);
            bb[tn][1] = asu(bp[4 * BS_STRIDE]);
        }
#pragma unroll
        for (int tm = 0; tm < 4; tm++)
#pragma unroll
            for (int tn = 0; tn < 8; tn++)
                mma_tf32(c[tm][tn], a[tm], bb[tn]);
    }
}

// ---------------- kernel A0: H0 = tf32(z @ W1[:128,:]) ----------------
__global__ void k_h0(const float* __restrict__ z, const float* __restrict__ W1) {
    __shared__ float zs[DIN];
    int n = blockIdx.x, t = threadIdx.x;
    if (t < DIN) zs[t] = z[n * DIN + t];
    __syncthreads();
    float acc = 0.f;
#pragma unroll 8
    for (int d = 0; d < DIN; d++) acc += zs[d] * W1[d * HID + t];
    g_H0[n * HID + t] = __uint_as_float(f2tf(acc));
}

// ---------------- kernel A: A[b] = relu(P[b]@H0 + corr⊗w1l) ----------------
__global__ void __launch_bounds__(128, 2)
k_A(const float* __restrict__ P, const float* __restrict__ W1) {
    extern __shared__ float sm[];
    float* As   = sm;                     // 3 * 4608
    float* Bs   = As + 3 * AS_BUF;        // 3 * 4352
    float* corr = Bs + 3 * BS_BUF;        // 128
    float* w1l  = corr + 128;             // 128

    const int m0 = blockIdx.x * 128, n0 = blockIdx.y * 128, b = blockIdx.z;
    const int tid = threadIdx.x, lane = tid & 31, wid = tid >> 5;  // 4 warps
    const int wm = wid >> 1, wn = wid & 1, g = lane >> 2, t4 = lane & 3;
    const int rA = wm * 64, cB = wn * 64;
    const float* Pb = P + (size_t)b * NN * NN;

    corr[tid] = Pb[(size_t)(m0 + tid) * NN + b];
    w1l[tid]  = W1[DIN * HID + n0 + tid];

    float cacc[4][8][4];
#pragma unroll
    for (int tm = 0; tm < 4; tm++)
#pragma unroll
        for (int tn = 0; tn < 8; tn++)
#pragma unroll
            for (int e = 0; e < 4; e++) cacc[tm][tn][e] = 0.f;

    // 3-stage cp.async pipeline over 12 k-tiles
    cp_tileA(As, Pb + (size_t)m0 * NN, NN, tid);
    cp_tileB(Bs, g_H0 + n0, HID, tid);
    cpa_commit();
    cp_tileA(As + AS_BUF, Pb + (size_t)m0 * NN + 32, NN, tid);
    cp_tileB(Bs + BS_BUF, g_H0 + 32 * HID + n0, HID, tid);
    cpa_commit();

#pragma unroll 1
    for (int kt = 0; kt < 12; kt++) {
        if (kt == 11) cpa_wait<0>(); else cpa_wait<1>();
        __syncthreads();
        if (kt < 10) {
            const int s = (kt + 2) % 3;
            cp_tileA(As + s * AS_BUF, Pb + (size_t)m0 * NN + (kt + 2) * 32, NN, tid);
            cp_tileB(Bs + s * BS_BUF, g_H0 + (size_t)(kt + 2) * 32 * HID + n0, HID, tid);
            cpa_commit();
        }
        const int cur = kt % 3;
        compute_ktile64(cacc, As + cur * AS_BUF, Bs + cur * BS_BUF, rA, cB, g, t4);
    }

    // epilogue: relu(c + corr[m]*w1l[n]) -> g_A (fp32)
#pragma unroll
    for (int tm = 0; tm < 4; tm++) {
        int r0 = rA + tm * 16 + g;
        float cr0 = corr[r0], cr1 = corr[r0 + 8];
#pragma unroll
        for (int tn = 0; tn < 8; tn++) {
            int c0 = cB + tn * 8 + 2 * t4;
            float w0 = w1l[c0], w1 = w1l[c0 + 1];
            float* o0 = g_A + ((size_t)b * NN + m0 + r0) * HID + n0 + c0;
            o0[0] = fmaxf(cacc[tm][tn][0] + cr0 * w0, 0.f);
            o0[1] = fmaxf(cacc[tm][tn][1] + cr0 * w1, 0.f);
            float* o1 = g_A + ((size_t)b * NN + m0 + r0 + 8) * HID + n0 + c0;
            o1[0] = fmaxf(cacc[tm][tn][2] + cr1 * w0, 0.f);
            o1[1] = fmaxf(cacc[tm][tn][3] + cr1 * w1, 0.f);
        }
    }
}

// ---------------- kernel T: t3[b] = W2 (W2^T (A_b^T u_b)) ----------------
__global__ void k_t3(const float* __restrict__ P, const float* __restrict__ W2) {
    __shared__ float u[NN];
    __shared__ float t1s[HID];
    __shared__ float t2s[HID2];
    const int b = blockIdx.x, tid = threadIdx.x;  // 256 threads
    for (int k = tid; k < NN; k += 256)
        u[k] = P[(size_t)b * NN * NN + (size_t)b * NN + k];
    __syncthreads();
    {
        float acc = 0.f;
        const float* Ab = g_A + (size_t)b * NN * HID + tid;
#pragma unroll 8
        for (int k = 0; k < NN; k++) acc += u[k] * Ab[(size_t)k * HID];
        t1s[tid] = acc;
    }
    __syncthreads();
    if (tid < HID2) {
        float acc = 0.f;
#pragma unroll 8
        for (int h = 0; h < HID; h++) acc += W2[(size_t)h * HID2 + tid] * t1s[h];
        t2s[tid] = acc;
    }
    __syncthreads();
    {
        float acc = 0.f;
        const float* w2r = W2 + (size_t)tid * HID2;
#pragma unroll 8
        for (int j = 0; j < HID2; j++) acc += w2r[j] * t2s[j];
        g_t3[b * HID + tid] = acc;
    }
}

// ---------------- kernel V: v[b,r] = <A[b,r,:], t3[b]> ----------------
__global__ void k_v(const float* __restrict__ P) {
    __shared__ float t3s[HID];
    const int b = blockIdx.x, tid = threadIdx.x;
    const int lane = tid & 31, wid = tid >> 5;   // 8 warps
    if (tid < HID) t3s[tid] = g_t3[b * HID + tid];
    __syncthreads();
    for (int r = wid; r < NN; r += 8) {
        const float* a = g_A + ((size_t)b * NN + r) * HID;
        float4 x0 = *(const float4*)(a + lane * 4);
        float4 x1 = *(const float4*)(a + 128 + lane * 4);
        float4 t0 = *(const float4*)(t3s + lane * 4);
        float4 t1 = *(const float4*)(t3s + 128 + lane * 4);
        float p = x0.x * t0.x + x0.y * t0.y + x0.z * t0.z + x0.w * t0.w
                + x1.x * t1.x + x1.y * t1.y + x1.z * t1.z + x1.w * t1.w;
#pragma unroll
        for (int o = 16; o > 0; o >>= 1) p += __shfl_xor_sync(0xffffffffu, p, o);
        if (lane == 0) g_v[b * NN + r] = p;
    }
}

// ---------------- kernel S2: S[b,j] = <P[b,j,:], v[b]> ----------------
__global__ void k_S2(const float* __restrict__ P) {
    __shared__ float vsm[NN];
    const int b = blockIdx.y, j0 = blockIdx.x * 128;
    const int tid = threadIdx.x, lane = tid & 31, wid = tid >> 5;  // 8 warps
    for (int k = tid; k < NN; k += 256) vsm[k] = g_v[b * NN + k];
    __syncthreads();
    for (int jj = wid; jj < 128; jj += 8) {
        const int j = j0 + jj;
        const float* pr = P + (size_t)b * NN * NN + (size_t)j * NN;
        float p = 0.f;
#pragma unroll
        for (int c = 0; c < 3; c++) {
            float4 xv = *(const float4*)(pr + c * 128 + lane * 4);
            float4 vv = *(const float4*)(vsm + c * 128 + lane * 4);
            p += xv.x * vv.x + xv.y * vv.y + xv.z * vv.z + xv.w * vv.w;
        }
#pragma unroll
        for (int o = 16; o > 0; o >>= 1) p += __shfl_xor_sync(0xffffffffu, p, o);
        if (lane == 0) g_S[(size_t)b * NN + j] = p;
    }
}

// ---------------- kernel E: out = x + 0.5*(tril(S)+tril(S)^T) ----------------
__global__ void k_out(const float* __restrict__ x, float* __restrict__ out) {
    int idx = blockIdx.x * 256 + threadIdx.x;
    int i = idx / NN, j = idx % NN;
    float s = (i > j) ? g_S[i * NN + j]
            : (i < j) ? g_S[j * NN + i]
                      : 2.f * g_S[i * NN + i];
    out[idx] = x[idx] + 0.5f * s;
}

// ---------------- launch ----------------
extern "C" void kernel_launch(void* const* d_in, const int* in_sizes, int n_in,
                              void* d_out, int out_size) {
    (void)in_sizes; (void)n_in; (void)out_size;
    const float* z  = (const float*)d_in[0];
    const float* x  = (const float*)d_in[1];
    const float* P  = (const float*)d_in[2];
    const float* W1 = (const float*)d_in[3];
    const float* W2 = (const float*)d_in[4];
    float* out = (float*)d_out;

    const int SMEM_A = (3 * (AS_BUF + BS_BUF) + 256) * 4;   // 108,544 B

    cudaFuncSetAttribute(k_A, cudaFuncAttributeMaxDynamicSharedMemorySize, SMEM_A);

    k_h0<<<NN, 256>>>(z, W1);
    k_A<<<dim3(3, 2, NN), 128, SMEM_A>>>(P, W1);
    k_t3<<<NN, 256>>>(P, W2);
    k_v<<<NN, 256>>>(P);
    k_S2<<<dim3(3, NN), 256>>>(P);
    k_out<<<NN * NN / 256, 256>>>(x, out);
}

// round 7
// speedup vs baseline: 1.1293x; 1.1293x over previous
#include <cuda_runtime.h>
#include <cuda_fp16.h>
#include <cstdint>
#include <cstddef>

#define NN   384
#define DIN  128
#define HID  256
#define HID2 128

// ---------------- scratch (device globals: allocation-free) ----------------
__device__ __half g_H0h[HID * NN];               // H0^T fp16 [h][node]
__device__ __half g_Ah [(size_t)NN * NN * HID];  // relu(P@H0 + corr) fp16 : 75.5 MB
__device__ float  g_t3[NN * HID];
__device__ float  g_v [NN * NN];
__device__ float  g_S [NN * NN];

// ---------------- helpers ----------------
__device__ __forceinline__ void mma_f16(float* c, const uint32_t* a, const uint32_t* b) {
    asm volatile(
        "mma.sync.aligned.m16n8k16.row.col.f32.f16.f16.f32 "
        "{%0,%1,%2,%3}, {%4,%5,%6,%7}, {%8,%9}, {%0,%1,%2,%3};\n"
        : "+f"(c[0]), "+f"(c[1]), "+f"(c[2]), "+f"(c[3])
        : "r"(a[0]), "r"(a[1]), "r"(a[2]), "r"(a[3]), "r"(b[0]), "r"(b[1]));
}
__device__ __forceinline__ void cpa16(uint32_t saddr, const void* gaddr) {
    asm volatile("cp.async.cg.shared.global [%0], [%1], 16;" :: "r"(saddr), "l"(gaddr));
}
__device__ __forceinline__ void cpa_commit() { asm volatile("cp.async.commit_group;"); }
template <int N>
__device__ __forceinline__ void cpa_wait() {
    asm volatile("cp.async.wait_group %0;" :: "n"(N));
}

#define TS 40           // smem tile row stride in halves (32 + 8 pad; 20 words -> conflict-free)
#define TILE_H (128 * TS)

// ---------------- kernel A0: H0^T(fp16) = z @ W1[:128,:] ----------------
__global__ void k_h0(const float* __restrict__ z, const float* __restrict__ W1) {
    __shared__ float zs[DIN];
    int n = blockIdx.x, t = threadIdx.x;   // t = h (256)
    if (t < DIN) zs[t] = z[n * DIN + t];
    __syncthreads();
    float acc = 0.f;
#pragma unroll 8
    for (int d = 0; d < DIN; d++) acc += zs[d] * W1[d * HID + t];
    g_H0h[t * NN + n] = __float2half_rn(acc);
}

// ---------------- kernel A: A[b] = relu(P[b]@H0 + corr⊗w1l), fp16 tensor ----------------
__global__ void __launch_bounds__(256, 1)
k_A(const float* __restrict__ P, const float* __restrict__ W1) {
    __shared__ __half As[2][TILE_H];   // P tile   128(m) x 32(k)
    __shared__ __half Bs[2][TILE_H];   // H0^T     128(n) x 32(k)
    __shared__ float corr[128], w1l[128];

    const int m0 = blockIdx.x * 128, n0 = blockIdx.y * 128, b = blockIdx.z;
    const int tid = threadIdx.x, lane = tid & 31, wid = tid >> 5;   // 8 warps
    const int wm = wid >> 1, wn = wid & 1, g = lane >> 2, t4 = lane & 3;
    const int rA = wm * 32, cB = wn * 64;
    const float* Pb = P + (size_t)b * NN * NN;

    if (tid < 128) {
        corr[tid] = Pb[(size_t)(m0 + tid) * NN + b];
        w1l[tid]  = W1[DIN * HID + n0 + tid];
    }

    float cacc[2][8][4];
#pragma unroll
    for (int tm = 0; tm < 2; tm++)
#pragma unroll
        for (int tn = 0; tn < 8; tn++)
#pragma unroll
            for (int e = 0; e < 4; e++) cacc[tm][tn][e] = 0.f;

    // per-thread chunk coords: 512 chunks of 8 cols; 2 per thread
    const int r0c = tid >> 2, q0 = tid & 3;
    const int r1c = (tid + 256) >> 2, q1 = (tid + 256) & 3;

    float4 pa[4];   // prefetch regs for A (P) tile: 2 chunks x 2 float4

    // ---- prologue: tile 0 ----
    {
        const float* s0 = Pb + (size_t)(m0 + r0c) * NN + q0 * 8;
        const float* s1 = Pb + (size_t)(m0 + r1c) * NN + q1 * 8;
        pa[0] = *(const float4*)(s0);  pa[1] = *(const float4*)(s0 + 4);
        pa[2] = *(const float4*)(s1);  pa[3] = *(const float4*)(s1 + 4);
        cpa16((uint32_t)__cvta_generic_to_shared(&Bs[0][r0c * TS + q0 * 8]),
              g_H0h + (size_t)(n0 + r0c) * NN + q0 * 8);
        cpa16((uint32_t)__cvta_generic_to_shared(&Bs[0][r1c * TS + q1 * 8]),
              g_H0h + (size_t)(n0 + r1c) * NN + q1 * 8);
        cpa_commit();
        // convert + store A tile 0
        __half h[8];
#pragma unroll
        for (int e = 0; e < 4; e++) { h[e] = __float2half_rn(((const float*)&pa[0])[e]);
                                      h[4 + e] = __float2half_rn(((const float*)&pa[1])[e]); }
        *(uint4*)(&As[0][r0c * TS + q0 * 8]) = *(uint4*)h;
#pragma unroll
        for (int e = 0; e < 4; e++) { h[e] = __float2half_rn(((const float*)&pa[2])[e]);
                                      h[4 + e] = __float2half_rn(((const float*)&pa[3])[e]); }
        *(uint4*)(&As[0][r1c * TS + q1 * 8]) = *(uint4*)h;
        cpa_wait<0>();
        __syncthreads();
    }

#pragma unroll 1
    for (int kt = 0; kt < 12; kt++) {
        const int cur = kt & 1, nxt = cur ^ 1;
        if (kt < 11) {
            const int k0 = (kt + 1) * 32;
            const float* s0 = Pb + (size_t)(m0 + r0c) * NN + k0 + q0 * 8;
            const float* s1 = Pb + (size_t)(m0 + r1c) * NN + k0 + q1 * 8;
            pa[0] = *(const float4*)(s0);  pa[1] = *(const float4*)(s0 + 4);
            pa[2] = *(const float4*)(s1);  pa[3] = *(const float4*)(s1 + 4);
            cpa16((uint32_t)__cvta_generic_to_shared(&Bs[nxt][r0c * TS + q0 * 8]),
                  g_H0h + (size_t)(n0 + r0c) * NN + k0 + q0 * 8);
            cpa16((uint32_t)__cvta_generic_to_shared(&Bs[nxt][r1c * TS + q1 * 8]),
                  g_H0h + (size_t)(n0 + r1c) * NN + k0 + q1 * 8);
            cpa_commit();
        }
        // compute current k-tile: 2 x k16 steps
#pragma unroll
        for (int ks = 0; ks < 2; ks++) {
            const int kb = ks * 16;
            uint32_t a[2][4];
#pragma unroll
            for (int tm = 0; tm < 2; tm++) {
                const __half* ap = &As[cur][(rA + tm * 16 + g) * TS + kb + 2 * t4];
                a[tm][0] = *(const uint32_t*)(ap);
                a[tm][1] = *(const uint32_t*)(ap + 8 * TS);
                a[tm][2] = *(const uint32_t*)(ap + 8);
                a[tm][3] = *(const uint32_t*)(ap + 8 * TS + 8);
            }
            uint32_t bb[8][2];
#pragma unroll
            for (int tn = 0; tn < 8; tn++) {
                const __half* bp = &Bs[cur][(cB + tn * 8 + g) * TS + kb + 2 * t4];
                bb[tn][0] = *(const uint32_t*)(bp);
                bb[tn][1] = *(const uint32_t*)(bp + 8);
            }
#pragma unroll
            for (int tm = 0; tm < 2; tm++)
#pragma unroll
                for (int tn = 0; tn < 8; tn++)
                    mma_f16(cacc[tm][tn], a[tm], bb[tn]);
        }
        __syncthreads();
        if (kt < 11) {
            __half h[8];
#pragma unroll
            for (int e = 0; e < 4; e++) { h[e] = __float2half_rn(((const float*)&pa[0])[e]);
                                          h[4 + e] = __float2half_rn(((const float*)&pa[1])[e]); }
            *(uint4*)(&As[nxt][r0c * TS + q0 * 8]) = *(uint4*)h;
#pragma unroll
            for (int e = 0; e < 4; e++) { h[e] = __float2half_rn(((const float*)&pa[2])[e]);
                                          h[4 + e] = __float2half_rn(((const float*)&pa[3])[e]); }
            *(uint4*)(&As[nxt][r1c * TS + q1 * 8]) = *(uint4*)h;
            cpa_wait<0>();
            __syncthreads();
        }
    }

    // epilogue: relu(c + corr[m]*w1l[n]) -> g_Ah (fp16)
#pragma unroll
    for (int tm = 0; tm < 2; tm++) {
        int r0 = rA + tm * 16 + g;
        float cr0 = corr[r0], cr1 = corr[r0 + 8];
#pragma unroll
        for (int tn = 0; tn < 8; tn++) {
            int c0 = cB + tn * 8 + 2 * t4;
            float w0 = w1l[c0], w1 = w1l[c0 + 1];
            __half2* o0 = (__half2*)(g_Ah + ((size_t)b * NN + m0 + r0) * HID + n0 + c0);
            *o0 = __floats2half2_rn(fmaxf(cacc[tm][tn][0] + cr0 * w0, 0.f),
                                    fmaxf(cacc[tm][tn][1] + cr0 * w1, 0.f));
            __half2* o1 = (__half2*)(g_Ah + ((size_t)b * NN + m0 + r0 + 8) * HID + n0 + c0);
            *o1 = __floats2half2_rn(fmaxf(cacc[tm][tn][2] + cr1 * w0, 0.f),
                                    fmaxf(cacc[tm][tn][3] + cr1 * w1, 0.f));
        }
    }
}

// ---------------- kernel T: t3[b] = W2 (W2^T (A_b^T u_b)) ----------------
__global__ void k_t3(const float* __restrict__ P, const float* __restrict__ W2) {
    __shared__ float u[NN];
    __shared__ float t1s[HID];
    __shared__ float t2s[HID2];
    const int b = blockIdx.x, tid = threadIdx.x;  // 256 threads
    for (int k = tid; k < NN; k += 256)
        u[k] = P[(size_t)b * NN * NN + (size_t)b * NN + k];
    __syncthreads();
    {
        float acc = 0.f;
        const __half* Ab = g_Ah + (size_t)b * NN * HID + tid;
#pragma unroll 8
        for (int k = 0; k < NN; k++) acc += u[k] * __half2float(Ab[(size_t)k * HID]);
        t1s[tid] = acc;
    }
    __syncthreads();
    if (tid < HID2) {
        float acc = 0.f;
#pragma unroll 8
        for (int h = 0; h < HID; h++) acc += W2[(size_t)h * HID2 + tid] * t1s[h];
        t2s[tid] = acc;
    }
    __syncthreads();
    {
        float acc = 0.f;
        const float* w2r = W2 + (size_t)tid * HID2;
#pragma unroll 8
        for (int j = 0; j < HID2; j++) acc += w2r[j] * t2s[j];
        g_t3[b * HID + tid] = acc;
    }
}

// ---------------- kernel V: v[b,r] = <A[b,r,:], t3[b]> ----------------
__global__ void k_v(const float* __restrict__ P) {
    __shared__ float t3s[HID];
    const int b = blockIdx.x, tid = threadIdx.x;
    const int lane = tid & 31, wid = tid >> 5;   // 8 warps
    if (tid < HID) t3s[tid] = g_t3[b * HID + tid];
    __syncthreads();
    for (int r = wid; r < NN; r += 8) {
        const __half* a = g_Ah + ((size_t)b * NN + r) * HID;
        uint4 raw = *(const uint4*)(a + lane * 8);   // 8 halves
        float p = 0.f;
        const uint32_t* rw = (const uint32_t*)&raw;
#pragma unroll
        for (int j = 0; j < 4; j++) {
            float2 f = __half22float2(*(const __half2*)&rw[j]);
            p += f.x * t3s[lane * 8 + 2 * j] + f.y * t3s[lane * 8 + 2 * j + 1];
        }
#pragma unroll
        for (int o = 16; o > 0; o >>= 1) p += __shfl_xor_sync(0xffffffffu, p, o);
        if (lane == 0) g_v[b * NN + r] = p;
    }
}

// ---------------- kernel S2: S[b,j] = <P[b,j,:], v[b]> ----------------
__global__ void k_S2(const float* __restrict__ P) {
    __shared__ float vsm[NN];
    const int b = blockIdx.y, j0 = blockIdx.x * 128;
    const int tid = threadIdx.x, lane = tid & 31, wid = tid >> 5;  // 8 warps
    for (int k = tid; k < NN; k += 256) vsm[k] = g_v[b * NN + k];
    __syncthreads();
    for (int jj = wid; jj < 128; jj += 8) {
        const int j = j0 + jj;
        const float* pr = P + (size_t)b * NN * NN + (size_t)j * NN;
        float p = 0.f;
#pragma unroll
        for (int c = 0; c < 3; c++) {
            float4 xv = *(const float4*)(pr + c * 128 + lane * 4);
            float4 vv = *(const float4*)(vsm + c * 128 + lane * 4);
            p += xv.x * vv.x + xv.y * vv.y + xv.z * vv.z + xv.w * vv.w;
        }
#pragma unroll
        for (int o = 16; o > 0; o >>= 1) p += __shfl_xor_sync(0xffffffffu, p, o);
        if (lane == 0) g_S[(size_t)b * NN + j] = p;
    }
}

// ---------------- kernel E: out = x + 0.5*(tril(S)+tril(S)^T) ----------------
__global__ void k_out(const float* __restrict__ x, float* __restrict__ out) {
    int idx = blockIdx.x * 256 + threadIdx.x;
    int i = idx / NN, j = idx % NN;
    float s = (i > j) ? g_S[i * NN + j]
            : (i < j) ? g_S[j * NN + i]
                      : 2.f * g_S[i * NN + i];
    out[idx] = x[idx] + 0.5f * s;
}

// ---------------- launch ----------------
extern "C" void kernel_launch(void* const* d_in, const int* in_sizes, int n_in,
                              void* d_out, int out_size) {
    (void)in_sizes; (void)n_in; (void)out_size;
    const float* z  = (const float*)d_in[0];
    const float* x  = (const float*)d_in[1];
    const float* P  = (const float*)d_in[2];
    const float* W1 = (const float*)d_in[3];
    const float* W2 = (const float*)d_in[4];
    float* out = (float*)d_out;

    k_h0<<<NN, 256>>>(z, W1);
    k_A<<<dim3(3, 2, NN), 256>>>(P, W1);
    k_t3<<<NN, 256>>>(P, W2);
    k_v<<<NN, 256>>>(P);
    k_S2<<<dim3(3, NN), 256>>>(P);
    k_out<<<NN * NN / 256, 256>>>(x, out);
}

// round 8
// speedup vs baseline: 1.1296x; 1.0003x over previous
#include <cuda_runtime.h>
#include <cuda_fp16.h>
#include <cstdint>
#include <cstddef>

#define NN   384
#define DIN  128
#define HID  256
#define HID2 128

// ---------------- scratch (device globals: allocation-free) ----------------
__device__ __half g_H0h[HID * NN];               // H0^T fp16 [h][node]
__device__ __half g_Ah [(size_t)NN * NN * HID];  // relu(P@H0 + corr) fp16 : 75.5 MB
__device__ float  g_t3[NN * HID];
__device__ float  g_v [NN * NN];
__device__ float  g_S [NN * NN];

// ---------------- helpers ----------------
__device__ __forceinline__ void mma_f16(float* c, const uint32_t* a, const uint32_t* b) {
    asm volatile(
        "mma.sync.aligned.m16n8k16.row.col.f32.f16.f16.f32 "
        "{%0,%1,%2,%3}, {%4,%5,%6,%7}, {%8,%9}, {%0,%1,%2,%3};\n"
        : "+f"(c[0]), "+f"(c[1]), "+f"(c[2]), "+f"(c[3])
        : "r"(a[0]), "r"(a[1]), "r"(a[2]), "r"(a[3]), "r"(b[0]), "r"(b[1]));
}
__device__ __forceinline__ void cpa16(uint32_t saddr, const void* gaddr) {
    asm volatile("cp.async.cg.shared.global [%0], [%1], 16;" :: "r"(saddr), "l"(gaddr));
}
__device__ __forceinline__ void cpa_commit() { asm volatile("cp.async.commit_group;"); }
template <int N>
__device__ __forceinline__ void cpa_wait() {
    asm volatile("cp.async.wait_group %0;" :: "n"(N));
}

#define TS 40           // smem tile row stride in halves (32 + 8 pad; 20 words -> conflict-free)
#define TILE_H (128 * TS)

// ---------------- kernel A0: H0^T(fp16) = z @ W1[:128,:] ----------------
__global__ void k_h0(const float* __restrict__ z, const float* __restrict__ W1) {
    __shared__ float zs[DIN];
    int n = blockIdx.x, t = threadIdx.x;   // t = h (256)
    if (t < DIN) zs[t] = z[n * DIN + t];
    __syncthreads();
    float acc = 0.f;
#pragma unroll 8
    for (int d = 0; d < DIN; d++) acc += zs[d] * W1[d * HID + t];
    g_H0h[t * NN + n] = __float2half_rn(acc);
}

// ---------------- kernel A: A[b] = relu(P[b]@H0 + corr⊗w1l), fp16 tensor ----------------
__global__ void __launch_bounds__(256, 1)
k_A(const float* __restrict__ P, const float* __restrict__ W1) {
    __shared__ __half As[2][TILE_H];   // P tile   128(m) x 32(k)
    __shared__ __half Bs[2][TILE_H];   // H0^T     128(n) x 32(k)
    __shared__ float corr[128], w1l[128];

    const int m0 = blockIdx.x * 128, n0 = blockIdx.y * 128, b = blockIdx.z;
    const int tid = threadIdx.x, lane = tid & 31, wid = tid >> 5;   // 8 warps
    const int wm = wid >> 1, wn = wid & 1, g = lane >> 2, t4 = lane & 3;
    const int rA = wm * 32, cB = wn * 64;
    const float* Pb = P + (size_t)b * NN * NN;

    if (tid < 128) {
        corr[tid] = Pb[(size_t)(m0 + tid) * NN + b];
        w1l[tid]  = W1[DIN * HID + n0 + tid];
    }

    float cacc[2][8][4];
#pragma unroll
    for (int tm = 0; tm < 2; tm++)
#pragma unroll
        for (int tn = 0; tn < 8; tn++)
#pragma unroll
            for (int e = 0; e < 4; e++) cacc[tm][tn][e] = 0.f;

    // per-thread chunk coords: 512 chunks of 8 cols; 2 per thread
    const int r0c = tid >> 2, q0 = tid & 3;
    const int r1c = (tid + 256) >> 2, q1 = (tid + 256) & 3;

    float4 pa[4];   // prefetch regs for A (P) tile: 2 chunks x 2 float4

    // ---- prologue: tile 0 ----
    {
        const float* s0 = Pb + (size_t)(m0 + r0c) * NN + q0 * 8;
        const float* s1 = Pb + (size_t)(m0 + r1c) * NN + q1 * 8;
        pa[0] = *(const float4*)(s0);  pa[1] = *(const float4*)(s0 + 4);
        pa[2] = *(const float4*)(s1);  pa[3] = *(const float4*)(s1 + 4);
        cpa16((uint32_t)__cvta_generic_to_shared(&Bs[0][r0c * TS + q0 * 8]),
              g_H0h + (size_t)(n0 + r0c) * NN + q0 * 8);
        cpa16((uint32_t)__cvta_generic_to_shared(&Bs[0][r1c * TS + q1 * 8]),
              g_H0h + (size_t)(n0 + r1c) * NN + q1 * 8);
        cpa_commit();
        // convert + store A tile 0
        __half h[8];
#pragma unroll
        for (int e = 0; e < 4; e++) { h[e] = __float2half_rn(((const float*)&pa[0])[e]);
                                      h[4 + e] = __float2half_rn(((const float*)&pa[1])[e]); }
        *(uint4*)(&As[0][r0c * TS + q0 * 8]) = *(uint4*)h;
#pragma unroll
        for (int e = 0; e < 4; e++) { h[e] = __float2half_rn(((const float*)&pa[2])[e]);
                                      h[4 + e] = __float2half_rn(((const float*)&pa[3])[e]); }
        *(uint4*)(&As[0][r1c * TS + q1 * 8]) = *(uint4*)h;
        cpa_wait<0>();
        __syncthreads();
    }

#pragma unroll 1
    for (int kt = 0; kt < 12; kt++) {
        const int cur = kt & 1, nxt = cur ^ 1;
        if (kt < 11) {
            const int k0 = (kt + 1) * 32;
            const float* s0 = Pb + (size_t)(m0 + r0c) * NN + k0 + q0 * 8;
            const float* s1 = Pb + (size_t)(m0 + r1c) * NN + k0 + q1 * 8;
            pa[0] = *(const float4*)(s0);  pa[1] = *(const float4*)(s0 + 4);
            pa[2] = *(const float4*)(s1);  pa[3] = *(const float4*)(s1 + 4);
            cpa16((uint32_t)__cvta_generic_to_shared(&Bs[nxt][r0c * TS + q0 * 8]),
                  g_H0h + (size_t)(n0 + r0c) * NN + k0 + q0 * 8);
            cpa16((uint32_t)__cvta_generic_to_shared(&Bs[nxt][r1c * TS + q1 * 8]),
                  g_H0h + (size_t)(n0 + r1c) * NN + k0 + q1 * 8);
            cpa_commit();
        }
        // compute current k-tile: 2 x k16 steps
#pragma unroll
        for (int ks = 0; ks < 2; ks++) {
            const int kb = ks * 16;
            uint32_t a[2][4];
#pragma unroll
            for (int tm = 0; tm < 2; tm++) {
                const __half* ap = &As[cur][(rA + tm * 16 + g) * TS + kb + 2 * t4];
                a[tm][0] = *(const uint32_t*)(ap);
                a[tm][1] = *(const uint32_t*)(ap + 8 * TS);
                a[tm][2] = *(const uint32_t*)(ap + 8);
                a[tm][3] = *(const uint32_t*)(ap + 8 * TS + 8);
            }
            uint32_t bb[8][2];
#pragma unroll
            for (int tn = 0; tn < 8; tn++) {
                const __half* bp = &Bs[cur][(cB + tn * 8 + g) * TS + kb + 2 * t4];
                bb[tn][0] = *(const uint32_t*)(bp);
                bb[tn][1] = *(const uint32_t*)(bp + 8);
            }
#pragma unroll
            for (int tm = 0; tm < 2; tm++)
#pragma unroll
                for (int tn = 0; tn < 8; tn++)
                    mma_f16(cacc[tm][tn], a[tm], bb[tn]);
        }
        __syncthreads();
        if (kt < 11) {
            __half h[8];
#pragma unroll
            for (int e = 0; e < 4; e++) { h[e] = __float2half_rn(((const float*)&pa[0])[e]);
                                          h[4 + e] = __float2half_rn(((const float*)&pa[1])[e]); }
            *(uint4*)(&As[nxt][r0c * TS + q0 * 8]) = *(uint4*)h;
#pragma unroll
            for (int e = 0; e < 4; e++) { h[e] = __float2half_rn(((const float*)&pa[2])[e]);
                                          h[4 + e] = __float2half_rn(((const float*)&pa[3])[e]); }
            *(uint4*)(&As[nxt][r1c * TS + q1 * 8]) = *(uint4*)h;
            cpa_wait<0>();
            __syncthreads();
        }
    }

    // epilogue: relu(c + corr[m]*w1l[n]) -> g_Ah (fp16)
#pragma unroll
    for (int tm = 0; tm < 2; tm++) {
        int r0 = rA + tm * 16 + g;
        float cr0 = corr[r0], cr1 = corr[r0 + 8];
#pragma unroll
        for (int tn = 0; tn < 8; tn++) {
            int c0 = cB + tn * 8 + 2 * t4;
            float w0 = w1l[c0], w1 = w1l[c0 + 1];
            __half2* o0 = (__half2*)(g_Ah + ((size_t)b * NN + m0 + r0) * HID + n0 + c0);
            *o0 = __floats2half2_rn(fmaxf(cacc[tm][tn][0] + cr0 * w0, 0.f),
                                    fmaxf(cacc[tm][tn][1] + cr0 * w1, 0.f));
            __half2* o1 = (__half2*)(g_Ah + ((size_t)b * NN + m0 + r0 + 8) * HID + n0 + c0);
            *o1 = __floats2half2_rn(fmaxf(cacc[tm][tn][2] + cr1 * w0, 0.f),
                                    fmaxf(cacc[tm][tn][3] + cr1 * w1, 0.f));
        }
    }
}

// ---------------- kernel T: t3[b] = W2 (W2^T (A_b^T u_b)) ----------------
__global__ void k_t3(const float* __restrict__ P, const float* __restrict__ W2) {
    __shared__ float u[NN];
    __shared__ float t1s[HID];
    __shared__ float t2s[HID2];
    const int b = blockIdx.x, tid = threadIdx.x;  // 256 threads
    for (int k = tid; k < NN; k += 256)
        u[k] = P[(size_t)b * NN * NN + (size_t)b * NN + k];
    __syncthreads();
    {
        float acc = 0.f;
        const __half* Ab = g_Ah + (size_t)b * NN * HID + tid;
#pragma unroll 8
        for (int k = 0; k < NN; k++) acc += u[k] * __half2float(Ab[(size_t)k * HID]);
        t1s[tid] = acc;
    }
    __syncthreads();
    if (tid < HID2) {
        float acc = 0.f;
#pragma unroll 8
        for (int h = 0; h < HID; h++) acc += W2[(size_t)h * HID2 + tid] * t1s[h];
        t2s[tid] = acc;
    }
    __syncthreads();
    {
        float acc = 0.f;
        const float* w2r = W2 + (size_t)tid * HID2;
#pragma unroll 8
        for (int j = 0; j < HID2; j++) acc += w2r[j] * t2s[j];
        g_t3[b * HID + tid] = acc;
    }
}

// ---------------- kernel V: v[b,r] = <A[b,r,:], t3[b]> ----------------
__global__ void k_v(const float* __restrict__ P) {
    __shared__ float t3s[HID];
    const int b = blockIdx.x, tid = threadIdx.x;
    const int lane = tid & 31, wid = tid >> 5;   // 8 warps
    if (tid < HID) t3s[tid] = g_t3[b * HID + tid];
    __syncthreads();
    for (int r = wid; r < NN; r += 8) {
        const __half* a = g_Ah + ((size_t)b * NN + r) * HID;
        uint4 raw = *(const uint4*)(a + lane * 8);   // 8 halves
        float p = 0.f;
        const uint32_t* rw = (const uint32_t*)&raw;
#pragma unroll
        for (int j = 0; j < 4; j++) {
            float2 f = __half22float2(*(const __half2*)&rw[j]);
            p += f.x * t3s[lane * 8 + 2 * j] + f.y * t3s[lane * 8 + 2 * j + 1];
        }
#pragma unroll
        for (int o = 16; o > 0; o >>= 1) p += __shfl_xor_sync(0xffffffffu, p, o);
        if (lane == 0) g_v[b * NN + r] = p;
    }
}

// ---------------- kernel S2: S[b,j] = <P[b,j,:], v[b]> ----------------
__global__ void k_S2(const float* __restrict__ P) {
    __shared__ float vsm[NN];
    const int b = blockIdx.y, j0 = blockIdx.x * 128;
    const int tid = threadIdx.x, lane = tid & 31, wid = tid >> 5;  // 8 warps
    for (int k = tid; k < NN; k += 256) vsm[k] = g_v[b * NN + k];
    __syncthreads();
    for (int jj = wid; jj < 128; jj += 8) {
        const int j = j0 + jj;
        const float* pr = P + (size_t)b * NN * NN + (size_t)j * NN;
        float p = 0.f;
#pragma unroll
        for (int c = 0; c < 3; c++) {
            float4 xv = *(const float4*)(pr + c * 128 + lane * 4);
            float4 vv = *(const float4*)(vsm + c * 128 + lane * 4);
            p += xv.x * vv.x + xv.y * vv.y + xv.z * vv.z + xv.w * vv.w;
        }
#pragma unroll
        for (int o = 16; o > 0; o >>= 1) p += __shfl_xor_sync(0xffffffffu, p, o);
        if (lane == 0) g_S[(size_t)b * NN + j] = p;
    }
}

// ---------------- kernel E: out = x + 0.5*(tril(S)+tril(S)^T) ----------------
__global__ void k_out(const float* __restrict__ x, float* __restrict__ out) {
    int idx = blockIdx.x * 256 + threadIdx.x;
    int i = idx / NN, j = idx % NN;
    float s = (i > j) ? g_S[i * NN + j]
            : (i < j) ? g_S[j * NN + i]
                      : 2.f * g_S[i * NN + i];
    out[idx] = x[idx] + 0.5f * s;
}

// ---------------- launch ----------------
extern "C" void kernel_launch(void* const* d_in, const int* in_sizes, int n_in,
                              void* d_out, int out_size) {
    (void)in_sizes; (void)n_in; (void)out_size;
    const float* z  = (const float*)d_in[0];
    const float* x  = (const float*)d_in[1];
    const float* P  = (const float*)d_in[2];
    const float* W1 = (const float*)d_in[3];
    const float* W2 = (const float*)d_in[4];
    float* out = (float*)d_out;

    k_h0<<<NN, 256>>>(z, W1);
    k_A<<<dim3(3, 2, NN), 256>>>(P, W1);
    k_t3<<<NN, 256>>>(P, W2);
    k_v<<<NN, 256>>>(P);
    k_S2<<<dim3(3, NN), 256>>>(P);
    k_out<<<NN * NN / 256, 256>>>(x, out);
}